// round 11
// baseline (speedup 1.0000x reference)
#include <cuda_runtime.h>
#include <cuda_bf16.h>
#include <cstdint>

// GIB_Layer: M=50000 queries, K=32 support, 4 kinds x G=8 gaussian basis fns,
// masked mean over K, then (32 x 16) mixing matmul. REACH=1, EPS=1e-8.
//
// R10: exact R4 base (warp per query, grid-stride, QPW=8/WPB=4, hoisted
// coefficients + 16-reg lambda slice with 1/K folded in, parity-aligned
// gather, ballot-compacted exp, pure-shuffle epilogue) with two additions:
//   1. Split-gather: each scattered warp-LDG is forced into TWO
//      complementary half-warp-predicated LDGs (inline asm @p/@!p) so each
//      LDG touches ~16 lines. Per SASS_QUICKREF, within-LDG replays cost
//      2.07 cyc/wavefront vs 1.0 cross-LDG; splitting converts the gather's
//      64 within-LDG wavefronts toward the 1.0 rate.
//   2. bal==0 fast path (~7% of queries): store zeros, skip epilogue.

#define GIB_K     32
#define GIB_OBS   16
#define GIB_F     32          // 4*G features
#define GIB_EPS   1e-8f
#define WPB       4           // warps per block
#define QPW       8           // target queries per warp
#define LOG2E     1.4426950408889634f

__device__ __forceinline__ float fast_exp2(float x) {
    float y;
    asm("ex2.approx.ftz.f32 %0, %1;" : "=f"(y) : "f"(x));
    return y;
}

__global__ __launch_bounds__(WPB * 32)
void gib_layer_kernel(const float* __restrict__ points,
                      const float* __restrict__ q_coords,
                      const int*   __restrict__ support_idxs,
                      const float* __restrict__ cy_radius,
                      const float* __restrict__ disk_radius,
                      const float* __restrict__ disk_width,
                      const float* __restrict__ cone_radius,
                      const float* __restrict__ cone_inc,
                      const float* __restrict__ ellip_radii,
                      const float* __restrict__ lambdas,
                      float* __restrict__ out,
                      int M)
{
    const int lane      = threadIdx.x & 31;
    const int warp_glb  = (blockIdx.x * WPB) + (threadIdx.x >> 5);
    const int num_warps = gridDim.x * WPB;

    // ---- per-lane weight coefficients (query-invariant):
    // lane -> (kind = lane>>3, g = lane&7); unified base-2 exponent
    //   a*x2 + b*y2 + c*z2 + d*rz + k0,  rz = sqrt(x2+y2+EPS)*z
    const int kind = lane >> 3;
    const int g    = lane & 7;
    float a, b, c, d, k0;
    {
        const float NHL = -0.5f * LOG2E;
        if (kind == 0) {                  // cylinder
            float r = cy_radius[g];
            float P = NHL / (r * r + GIB_EPS);
            a = P; b = P; c = 0.f; d = 0.f; k0 = 0.f;
        } else if (kind == 1) {           // cone
            float r   = cone_radius[g];
            float inc = cone_inc[g];
            float Q = NHL / (r * r + GIB_EPS);
            a = Q; b = Q; c = Q * inc * inc; d = -2.f * Q * inc; k0 = Q * GIB_EPS;
        } else if (kind == 2) {           // disk
            float dr = disk_radius[g], dw = disk_width[g];
            float Dr = NHL / (dr * dr + GIB_EPS);
            float Dw = NHL / (dw * dw + GIB_EPS);
            a = Dr; b = Dr; c = Dw; d = 0.f; k0 = 0.f;
        } else {                          // ellipsoid
            float ra = ellip_radii[g * 3 + 0];
            float rb = ellip_radii[g * 3 + 1];
            float rc = ellip_radii[g * 3 + 2];
            a = NHL / (ra * ra + GIB_EPS);
            b = NHL / (rb * rb + GIB_EPS);
            c = NHL / (rc * rc + GIB_EPS);
            d = 0.f; k0 = 0.f;
        }
    }

    // ---- per-lane lambda slice (query-invariant), 1/K folded in.
    // lane l handles output o=l&15 over features f=(l&16)+j, j=0..15.
    const int o_idx = lane & 15;
    const int f0    = lane & 16;
    float lam[16];
    #pragma unroll
    for (int j = 0; j < 16; j++)
        lam[j] = lambdas[(f0 + j) * GIB_OBS + o_idx] * (1.0f / (float)GIB_K);

    // ---- query loop (grid-stride): whole warp shares one m per iteration.
    for (int m = warp_glb; m < M; m += num_warps) {
        const int pi  = support_idxs[m * GIB_K + lane];
        const int odd = pi & 1;
        // pi even: v2 = (x,y) at 12*pi,   vs = z at +8
        // pi odd:  v2 = (y,z) at 12*pi+4, vs = x at +0
        const float* pa = points + 3 * pi + odd;
        const float* pb = points + 3 * pi + (odd ? 0 : 2);

        // Split-gather: two complementary half-warp-predicated LDGs per
        // logical load, so each SASS LDG touches ~16 cache lines instead
        // of 32 (within-LDG replay rate 2.07 cyc/wf -> cross-LDG 1.0).
        float vx, vy;
        asm volatile("{\n\t"
            ".reg .pred p;\n\t"
            "setp.lt.s32 p, %3, 16;\n\t"
            "@p  ld.global.nc.v2.f32 {%0,%1}, [%2];\n\t"
            "@!p ld.global.nc.v2.f32 {%0,%1}, [%2];\n\t"
            "}" : "=f"(vx), "=f"(vy) : "l"(pa), "r"(lane));
        float vs;
        asm volatile("{\n\t"
            ".reg .pred p;\n\t"
            "setp.lt.s32 p, %2, 16;\n\t"
            "@p  ld.global.nc.f32 %0, [%1];\n\t"
            "@!p ld.global.nc.f32 %0, [%1];\n\t"
            "}" : "=f"(vs) : "l"(pb), "r"(lane));

        const float qx = q_coords[3 * m + 0];
        const float qy = q_coords[3 * m + 1];
        const float qz = q_coords[3 * m + 2];

        const float x = (odd ? vs : vx) - qx;
        const float y = (odd ? vx : vy) - qy;
        const float z = (odd ? vy : vs) - qz;

        const float x2 = x * x, y2 = y * y, z2 = z * z;
        const float d2 = x2 + y2 + z2;
        const float rz = sqrtf(x2 + y2 + GIB_EPS) * z;

        unsigned bal = __ballot_sync(0xffffffffu, d2 <= 1.0f);   // REACH^2=1

        if (bal == 0u) {                  // warp-uniform: no active neighbor
            if (lane < GIB_OBS)
                out[m * GIB_OBS + lane] = 0.f;
            continue;
        }

        float acc = 0.f;
        do {
            const int j = __ffs(bal) - 1;
            bal &= bal - 1;
            const float bx2 = __shfl_sync(0xffffffffu, x2, j);
            const float by2 = __shfl_sync(0xffffffffu, y2, j);
            const float bz2 = __shfl_sync(0xffffffffu, z2, j);
            const float brz = __shfl_sync(0xffffffffu, rz, j);
            const float arg = fmaf(a, bx2, fmaf(b, by2, fmaf(c, bz2, fmaf(d, brz, k0))));
            acc += fast_exp2(arg);
        } while (bal);
        // 1/K folded into lam

        // ---- epilogue: out[m, o] = sum_f feat[f] * lambdas[f, o].
        float oacc = 0.f;
        #pragma unroll
        for (int j = 0; j < 16; j++) {
            const float bf = __shfl_sync(0xffffffffu, acc, f0 | j);
            oacc = fmaf(bf, lam[j], oacc);
        }
        oacc += __shfl_xor_sync(0xffffffffu, oacc, 16);

        if (lane < GIB_OBS)
            out[m * GIB_OBS + lane] = oacc;
    }
}

extern "C" void kernel_launch(void* const* d_in, const int* in_sizes, int n_in,
                              void* d_out, int out_size)
{
    const float* points       = (const float*)d_in[0];
    const float* q_coords     = (const float*)d_in[1];
    const int*   support_idxs = (const int*)  d_in[2];
    const float* cy_radius    = (const float*)d_in[3];
    const float* disk_radius  = (const float*)d_in[4];
    const float* disk_width   = (const float*)d_in[5];
    const float* cone_radius  = (const float*)d_in[6];
    const float* cone_inc     = (const float*)d_in[7];
    const float* ellip_radii  = (const float*)d_in[8];
    const float* lambdas      = (const float*)d_in[9];
    float* out = (float*)d_out;

    const int M = in_sizes[1] / 3;        // q_coords is (M, 3)
    int blocks = (M + (WPB * QPW) - 1) / (WPB * QPW);
    if (blocks < 1) blocks = 1;

    gib_layer_kernel<<<blocks, WPB * 32>>>(points, q_coords, support_idxs,
                                           cy_radius, disk_radius, disk_width,
                                           cone_radius, cone_inc, ellip_radii,
                                           lambdas, out, M);
}

// round 13
// speedup vs baseline: 1.1951x; 1.1951x over previous
#include <cuda_runtime.h>
#include <cuda_bf16.h>
#include <cstdint>

// GIB_Layer: M=50000 queries, K=32 support, 4 kinds x G=8 gaussian basis fns,
// masked mean over K, then (32 x 16) mixing matmul. REACH=1, EPS=1e-8.
//
// R12: exact R4 base (warp per query, grid-stride, QPW=8/WPB=4, hoisted
// per-lane coefficients + 16-reg lambda slice with 1/K folded in,
// ballot-compacted exp, pure-shuffle 32x16 epilogue), with the gather
// rewritten to minimize L1tex wavefronts:
//   A = (3*pi) & ~3 (16B-aligned), off = (3*pi) & 3.
//   One LDG.128 at A always; one predicated LDG.64 at A+4 only for the
//   ~50% of lanes with off>=2 (point straddles the 16B chunk).
//   => ~48 wavefronts/query instead of 64 (2 scattered LDGs x 32 lines).
// Extraction is 9 SELs (FMA/ALU pipes have headroom). Branch-free.

#define GIB_K     32
#define GIB_OBS   16
#define GIB_F     32          // 4*G features
#define GIB_EPS   1e-8f
#define WPB       4           // warps per block
#define QPW       8           // target queries per warp
#define LOG2E     1.4426950408889634f

__device__ __forceinline__ float fast_exp2(float x) {
    float y;
    asm("ex2.approx.ftz.f32 %0, %1;" : "=f"(y) : "f"(x));
    return y;
}

__global__ __launch_bounds__(WPB * 32)
void gib_layer_kernel(const float* __restrict__ points,
                      const float* __restrict__ q_coords,
                      const int*   __restrict__ support_idxs,
                      const float* __restrict__ cy_radius,
                      const float* __restrict__ disk_radius,
                      const float* __restrict__ disk_width,
                      const float* __restrict__ cone_radius,
                      const float* __restrict__ cone_inc,
                      const float* __restrict__ ellip_radii,
                      const float* __restrict__ lambdas,
                      float* __restrict__ out,
                      int M)
{
    const int lane      = threadIdx.x & 31;
    const int warp_glb  = (blockIdx.x * WPB) + (threadIdx.x >> 5);
    const int num_warps = gridDim.x * WPB;

    // ---- per-lane weight coefficients (query-invariant):
    // lane -> (kind = lane>>3, g = lane&7); unified base-2 exponent
    //   a*x2 + b*y2 + c*z2 + d*rz + k0,  rz = sqrt(x2+y2+EPS)*z
    const int kind = lane >> 3;
    const int g    = lane & 7;
    float a, b, c, d, k0;
    {
        const float NHL = -0.5f * LOG2E;
        if (kind == 0) {                  // cylinder
            float r = cy_radius[g];
            float P = NHL / (r * r + GIB_EPS);
            a = P; b = P; c = 0.f; d = 0.f; k0 = 0.f;
        } else if (kind == 1) {           // cone
            float r   = cone_radius[g];
            float inc = cone_inc[g];
            float Q = NHL / (r * r + GIB_EPS);
            a = Q; b = Q; c = Q * inc * inc; d = -2.f * Q * inc; k0 = Q * GIB_EPS;
        } else if (kind == 2) {           // disk
            float dr = disk_radius[g], dw = disk_width[g];
            float Dr = NHL / (dr * dr + GIB_EPS);
            float Dw = NHL / (dw * dw + GIB_EPS);
            a = Dr; b = Dr; c = Dw; d = 0.f; k0 = 0.f;
        } else {                          // ellipsoid
            float ra = ellip_radii[g * 3 + 0];
            float rb = ellip_radii[g * 3 + 1];
            float rc = ellip_radii[g * 3 + 2];
            a = NHL / (ra * ra + GIB_EPS);
            b = NHL / (rb * rb + GIB_EPS);
            c = NHL / (rc * rc + GIB_EPS);
            d = 0.f; k0 = 0.f;
        }
    }

    // ---- per-lane lambda slice (query-invariant), 1/K folded in.
    // lane l handles output o=l&15 over features f=(l&16)+j, j=0..15.
    const int o_idx = lane & 15;
    const int f0    = lane & 16;
    float lam[16];
    #pragma unroll
    for (int j = 0; j < 16; j++)
        lam[j] = lambdas[(f0 + j) * GIB_OBS + o_idx] * (1.0f / (float)GIB_K);

    // ---- query loop (grid-stride): whole warp shares one m per iteration.
    for (int m = warp_glb; m < M; m += num_warps) {
        const int pi  = support_idxs[m * GIB_K + lane];
        const int fi  = 3 * pi;            // float index of point.x
        const int off = fi & 3;            // 0..3 within the 16B chunk
        const int A   = fi & ~3;           // 16B-aligned float index

        // One LDG.128 always; one LDG.64 only when the point straddles
        // (off >= 2, ~50% of lanes). Both naturally aligned.
        const float4 v4 = *reinterpret_cast<const float4*>(points + A);
        float e0 = 0.f, e1 = 0.f;
        if (off >= 2) {
            const float2 e2 = *reinterpret_cast<const float2*>(points + A + 4);
            e0 = e2.x; e1 = e2.y;
        }

        // extract x,y,z = floats fi, fi+1, fi+2 = chunk floats off, off+1, off+2
        const bool b0 = (off & 1) != 0;
        const bool b1 = (off & 2) != 0;
        const float x01 = b0 ? v4.y : v4.x;   // off in {0,1}
        const float x23 = b0 ? v4.w : v4.z;   // off in {2,3}
        const float px  = b1 ? x23 : x01;
        const float y12 = b0 ? v4.z : v4.y;   // off+1 in {1,2}
        const float y34 = b0 ? e0   : v4.w;   // off+1 in {3,4}
        const float py  = b1 ? y34 : y12;
        const float z23 = b0 ? v4.w : v4.z;   // off+2 in {2,3}
        const float z45 = b0 ? e1   : e0;     // off+2 in {4,5}
        const float pz  = b1 ? z45 : z23;

        const float qx = q_coords[3 * m + 0];
        const float qy = q_coords[3 * m + 1];
        const float qz = q_coords[3 * m + 2];

        const float x = px - qx;
        const float y = py - qy;
        const float z = pz - qz;

        const float x2 = x * x, y2 = y * y, z2 = z * z;
        const float d2 = x2 + y2 + z2;
        const float rz = sqrtf(x2 + y2 + GIB_EPS) * z;

        unsigned bal = __ballot_sync(0xffffffffu, d2 <= 1.0f);   // REACH^2=1
        float acc = 0.f;
        while (bal) {
            const int j = __ffs(bal) - 1;
            bal &= bal - 1;
            const float bx2 = __shfl_sync(0xffffffffu, x2, j);
            const float by2 = __shfl_sync(0xffffffffu, y2, j);
            const float bz2 = __shfl_sync(0xffffffffu, z2, j);
            const float brz = __shfl_sync(0xffffffffu, rz, j);
            const float arg = fmaf(a, bx2, fmaf(b, by2, fmaf(c, bz2, fmaf(d, brz, k0))));
            acc += fast_exp2(arg);
        }
        // 1/K folded into lam

        // ---- epilogue: out[m, o] = sum_f feat[f] * lambdas[f, o].
        float oacc = 0.f;
        #pragma unroll
        for (int j = 0; j < 16; j++) {
            const float bf = __shfl_sync(0xffffffffu, acc, f0 | j);
            oacc = fmaf(bf, lam[j], oacc);
        }
        oacc += __shfl_xor_sync(0xffffffffu, oacc, 16);

        if (lane < GIB_OBS)
            out[m * GIB_OBS + lane] = oacc;
    }
}

extern "C" void kernel_launch(void* const* d_in, const int* in_sizes, int n_in,
                              void* d_out, int out_size)
{
    const float* points       = (const float*)d_in[0];
    const float* q_coords     = (const float*)d_in[1];
    const int*   support_idxs = (const int*)  d_in[2];
    const float* cy_radius    = (const float*)d_in[3];
    const float* disk_radius  = (const float*)d_in[4];
    const float* disk_width   = (const float*)d_in[5];
    const float* cone_radius  = (const float*)d_in[6];
    const float* cone_inc     = (const float*)d_in[7];
    const float* ellip_radii  = (const float*)d_in[8];
    const float* lambdas      = (const float*)d_in[9];
    float* out = (float*)d_out;

    const int M = in_sizes[1] / 3;        // q_coords is (M, 3)
    int blocks = (M + (WPB * QPW) - 1) / (WPB * QPW);
    if (blocks < 1) blocks = 1;

    gib_layer_kernel<<<blocks, WPB * 32>>>(points, q_coords, support_idxs,
                                           cy_radius, disk_radius, disk_width,
                                           cone_radius, cone_inc, ellip_radii,
                                           lambdas, out, M);
}